// round 16
// baseline (speedup 1.0000x reference)
#include <cuda_runtime.h>
#include <math.h>

// ---------------- problem constants ----------------
#define Nb    32
#define Pfr   75
#define NGRID 3
#define NFRAG 9
#define CROPS 64
#define PUZ   225
#define IMGS  224
#define PATCH 16
#define NPT   196
#define Dm    768
#define NHEAD 12
#define HD    64
#define NL    12
#define MLPD  3072
#define NCLS  1000
#define TOKS  197
#define ROWS  (Nb*TOKS)   // 6304

// ---------------- scratch (static device globals; no allocation) ----------------
__device__ float g_img[Nb*3*PUZ*PUZ];
__device__ float g_patches[(size_t)Nb*NPT*Dm];
__device__ float g_ptok[(size_t)Nb*NPT*Dm];
__device__ float g_tok[(size_t)ROWS*Dm];
__device__ float g_h[(size_t)ROWS*Dm];
__device__ float g_qkv[(size_t)ROWS*3*Dm];
__device__ float g_atto[(size_t)ROWS*Dm];
__device__ float g_mlp[(size_t)ROWS*MLPD];
__device__ float g_cls[Nb*Dm];
__device__ float g_feat[Nb*NCLS];
__device__ float g_fc1[Nb*NCLS];
__device__ int   g_shuffle[Nb*NFRAG];
__device__ int   g_offs[Nb*NFRAG*2];
__device__ int   g_jitt[Nb*NFRAG*3];

// ---------------- threefry2x32 (KAT-verified core) ----------------
__device__ __forceinline__ void threefry(unsigned k0, unsigned k1, unsigned &x0, unsigned &x1) {
    unsigned ks0 = k0, ks1 = k1, ks2 = k0 ^ k1 ^ 0x1BD11BDAu;
    x0 += ks0; x1 += ks1;
#define TFRND(r) { x0 += x1; x1 = (x1 << (r)) | (x1 >> (32 - (r))); x1 ^= x0; }
    TFRND(13) TFRND(15) TFRND(26) TFRND(6);  x0 += ks1; x1 += ks2 + 1u;
    TFRND(17) TFRND(29) TFRND(16) TFRND(24); x0 += ks2; x1 += ks0 + 2u;
    TFRND(13) TFRND(15) TFRND(26) TFRND(6);  x0 += ks0; x1 += ks1 + 3u;
    TFRND(17) TFRND(29) TFRND(16) TFRND(24); x0 += ks1; x1 += ks2 + 4u;
    TFRND(13) TFRND(15) TFRND(26) TFRND(6);  x0 += ks2; x1 += ks0 + 5u;
#undef TFRND
}

__device__ __forceinline__ unsigned rb32_part(unsigned k0, unsigned k1, unsigned i) {
    unsigned x0 = 0u, x1 = i;
    threefry(k0, k1, x0, x1);
    return x0 ^ x1;
}

__device__ __forceinline__ void split_key(unsigned k0, unsigned k1, unsigned t,
                                          unsigned &o0, unsigned &o1) {
    unsigned x0 = 0u, x1 = t;
    threefry(k0, k1, x0, x1);
    o0 = x0; o1 = x1;
}

// ---------------- kernel 1: RNG setup + target output ----------------
__global__ void rng_kernel(float* target_out) {
    __shared__ unsigned keys[14];
    __shared__ float noise[Nb*NFRAG];
    int tid = threadIdx.x;

    if (tid == 0) {
        for (int t = 0; t < 3; t++)
            split_key(0u, 42u, (unsigned)t, keys[2*t], keys[2*t+1]);
        split_key(keys[2], keys[3], 0u, keys[6],  keys[7]);
        split_key(keys[2], keys[3], 1u, keys[8],  keys[9]);
        split_key(keys[4], keys[5], 0u, keys[10], keys[11]);
        split_key(keys[4], keys[5], 1u, keys[12], keys[13]);
    }
    __syncthreads();

    if (tid < Nb*NFRAG) {
        unsigned bits = rb32_part(keys[0], keys[1], (unsigned)tid);
        noise[tid] = __uint_as_float((bits >> 9) | 0x3F800000u) - 1.0f;
    }
    __syncthreads();

    if (tid < Nb) {
        int ids[NFRAG];
        unsigned used = 0;
        for (int r = 0; r < NFRAG; r++) {
            int best = -1;
            for (int j = 0; j < NFRAG; j++) {
                if (used & (1u << j)) continue;
                if (best < 0 || noise[tid*NFRAG + j] < noise[tid*NFRAG + best]) best = j;
            }
            ids[r] = best; used |= (1u << best);
        }
        int rest[NFRAG];
        for (int r = 0; r < NFRAG; r++) { g_shuffle[tid*NFRAG + r] = ids[r]; rest[ids[r]] = r; }
        if (target_out) {
            for (int f = 0; f < NFRAG; f++) {
                target_out[(tid*NFRAG + f)*2 + 0] = (float)(rest[f] / 3);
                target_out[(tid*NFRAG + f)*2 + 1] = (float)(rest[f] % 3);
            }
        }
    }

    for (int i = tid; i < Nb*NFRAG*2; i += blockDim.x) {
        unsigned hi = rb32_part(keys[6], keys[7], (unsigned)i);
        unsigned lo = rb32_part(keys[8], keys[9], (unsigned)i);
        unsigned v = (((hi % 12u) * 4u) + (lo % 12u)) % 12u;
        g_offs[i] = (int)v;
    }
    for (int i = tid; i < Nb*NFRAG*3; i += blockDim.x) {
        unsigned hi = rb32_part(keys[10], keys[11], (unsigned)i);
        unsigned lo = rb32_part(keys[12], keys[13], (unsigned)i);
        unsigned v = ((hi % 5u) + (lo % 5u)) % 5u;
        g_jitt[i] = (int)v - 2;
    }
}

// ---------------- block reductions (blockDim == 256) ----------------
__device__ __forceinline__ float bsum256(float v, float* red8) {
    for (int o = 16; o; o >>= 1) v += __shfl_xor_sync(0xFFFFFFFFu, v, o);
    if ((threadIdx.x & 31) == 0) red8[threadIdx.x >> 5] = v;
    __syncthreads();
    float r = red8[0]+red8[1]+red8[2]+red8[3]+red8[4]+red8[5]+red8[6]+red8[7];
    __syncthreads();
    return r;
}

// ---------------- kernel 2: augment ----------------
__global__ void augment_kernel(const float* __restrict__ x) {
    __shared__ float buf[Pfr*Pfr];
    __shared__ float red8[8];
    int bfc = blockIdx.x;
    int c = bfc % 3;
    int bf = bfc / 3;
    int b = bf / NFRAG, f = bf % NFRAG;

    int src = g_shuffle[bf];
    int sr = (src / 3) * Pfr + g_offs[2*bf + 0];
    int sc = (src % 3) * Pfr + g_offs[2*bf + 1];
    float jitv = (float)g_jitt[bf*3 + c];
    const float* xp = x + ((size_t)b*3 + c) * PUZ * PUZ;

    const float sf = 64.0f / 75.0f;
    float lsum = 0.f;
    for (int idx = threadIdx.x; idx < Pfr*Pfr; idx += 256) {
        int i = idx / Pfr, j = idx % Pfr;
        float fy = (i + 0.5f) * sf - 0.5f;
        float fx = (j + 0.5f) * sf - 0.5f;
        int   y0 = (int)floorf(fy); float dy = fy - (float)y0;
        int   x0 = (int)floorf(fx); float dx = fx - (float)x0;
        int y0c = max(0, min(63, y0)),   y1c = max(0, min(63, y0 + 1));
        int x0c = max(0, min(63, x0)),   x1c = max(0, min(63, x0 + 1));
        const float* r0 = xp + (size_t)(sr + y0c) * PUZ + sc;
        const float* r1 = xp + (size_t)(sr + y1c) * PUZ + sc;
        float v = (1.f-dy)*((1.f-dx)*r0[x0c] + dx*r0[x1c])
                +       dy*((1.f-dx)*r1[x0c] + dx*r1[x1c]);
        v = v + jitv;
        v = fminf(fmaxf(v, 0.f), 255.f);
        buf[idx] = v;
        lsum += v;
    }
    float m = bsum256(lsum, red8) * (1.0f / (Pfr*Pfr));
    float lss = 0.f;
    for (int idx = threadIdx.x; idx < Pfr*Pfr; idx += 256) {
        float d = buf[idx] - m;
        lss += d * d;
    }
    float ss = bsum256(lss, red8);
    float s = sqrtf(ss / (float)(Pfr*Pfr - 1));
    if (s == 0.f) s = 1.f;

    int gi = f / 3, gj = f % 3;
    float* op = g_img + ((size_t)b*3 + c) * PUZ * PUZ + (size_t)gi*Pfr*PUZ + gj*Pfr;
    for (int idx = threadIdx.x; idx < Pfr*Pfr; idx += 256) {
        op[(idx / Pfr) * PUZ + (idx % Pfr)] = (buf[idx] - m) / s;
    }
}

// ---------------- kernel 3: patchify ----------------
__global__ void patchify_kernel() {
    int idx = blockIdx.x * blockDim.x + threadIdx.x;
    if (idx >= Nb*NPT*Dm) return;
    int k = idx % Dm;
    int p = (idx / Dm) % NPT;
    int b = idx / (Dm * NPT);
    int c = k >> 8, u = (k >> 4) & 15, v = k & 15;
    int pi = p / 14, pj = p % 14;
    g_patches[idx] = g_img[(((size_t)b*3 + c) * PUZ + (pi*16 + u)) * PUZ + (pj*16 + v)];
}

// ---------------- kernel 4: token assemble ----------------
__global__ void assemble_kernel(const float* __restrict__ clstok, const float* __restrict__ pos) {
    int idx = blockIdx.x * blockDim.x + threadIdx.x;
    if (idx >= Nb*TOKS*Dm) return;
    int d = idx % Dm;
    int t = (idx / Dm) % TOKS;
    int b = idx / (Dm * TOKS);
    float v = (t == 0) ? clstok[d] : g_ptok[((size_t)b*NPT + (t-1))*Dm + d];
    g_tok[idx] = v + pos[t*Dm + d];
}

// ---------------- kernel 5: layernorm ----------------
__global__ void ln_kernel(const float* __restrict__ x, long long sx,
                          const float* __restrict__ s, const float* __restrict__ b,
                          float* __restrict__ y, long long sy) {
    __shared__ float red8[8];
    const float* xr = x + (long long)blockIdx.x * sx;
    float* yr = y + (long long)blockIdx.x * sy;
    int t = threadIdx.x;
    float v0 = xr[t], v1 = xr[t+256], v2 = xr[t+512];
    float m = bsum256(v0+v1+v2, red8) * (1.0f/768.0f);
    float d0 = v0-m, d1 = v1-m, d2 = v2-m;
    float var = bsum256(d0*d0 + d1*d1 + d2*d2, red8) * (1.0f/768.0f);
    float inv = rsqrtf(var + 1e-6f);
    yr[t]     = d0*inv*s[t]     + b[t];
    yr[t+256] = d1*inv*s[t+256] + b[t+256];
    yr[t+512] = d2*inv*s[t+512] + b[t+512];
}

// ---------------- kernel 6a: small fp32 SGEMM (head only) ----------------
template<int ACT>
__global__ void sgemm_kernel(const float* __restrict__ A, const float* __restrict__ B,
                             const float* __restrict__ bias, float* __restrict__ C,
                             int M, int N, int K, int ACCUM) {
    __shared__ float As[16][64];
    __shared__ float Bs[16][64];
    int tid = threadIdx.x;
    int tx = tid & 15, ty = tid >> 4;
    int blockRow = blockIdx.y * 64;
    int blockCol = blockIdx.x * 64;
    float acc[4][4] = {};

    for (int k0 = 0; k0 < K; k0 += 16) {
        #pragma unroll
        for (int t = tid; t < 64*16; t += 256) {
            int m  = t >> 4, kk  = t & 15;
            int gr = blockRow + m, gc = k0 + kk;
            As[kk][m] = (gr < M && gc < K) ? A[(size_t)gr*K + gc] : 0.f;
            int kk2 = t >> 6, nn = t & 63;
            int gr2 = k0 + kk2, gc2 = blockCol + nn;
            Bs[kk2][nn] = (gr2 < K && gc2 < N) ? B[(size_t)gr2*N + gc2] : 0.f;
        }
        __syncthreads();
        #pragma unroll
        for (int kk = 0; kk < 16; kk++) {
            float a[4], bb[4];
            #pragma unroll
            for (int i = 0; i < 4; i++) a[i]  = As[kk][ty*4 + i];
            #pragma unroll
            for (int j = 0; j < 4; j++) bb[j] = Bs[kk][tx*4 + j];
            #pragma unroll
            for (int i = 0; i < 4; i++)
                #pragma unroll
                for (int j = 0; j < 4; j++)
                    acc[i][j] += a[i] * bb[j];
        }
        __syncthreads();
    }

    #pragma unroll
    for (int i = 0; i < 4; i++) {
        int r = blockRow + ty*4 + i;
        if (r >= M) continue;
        #pragma unroll
        for (int j = 0; j < 4; j++) {
            int cc = blockCol + tx*4 + j;
            if (cc >= N) continue;
            float v = acc[i][j] + (bias ? bias[cc] : 0.f);
            if (ACT == 1) v = 0.5f * v * (1.0f + erff(v * 0.70710678118654752f));
            if (ACT == 2) v = fmaxf(v, 0.f);
            size_t oi = (size_t)r * N + cc;
            if (ACCUM) C[oi] += v; else C[oi] = v;
        }
    }
}

// ---------------- kernel 6b: bf16x3 GEMM, pre-split packed smem, cp.async ----------------
// C[M,N] = act(A[M,K] @ B[K,N] + bias) [+= C]; N%128==0, K%32==0, M arbitrary.
#define GBM 128
#define GBN 128
#define GBK 32
#define ASTR 36        // fp32 staging A[m][k]
#define BSTR 132       // fp32 staging B[k][n]
#define ABUF (GBM*ASTR)            // 4608 floats
#define BBUF (GBK*BSTR)            // 4224 floats
#define PSTR 132                   // packed arrays [16 kpair][132]
#define PBUF (16*PSTR)             // 2112 unsigned
// smem: staging (ABUF+BBUF) floats + 4 packed arrays PBUF unsigned
#define GEMM_SMEM_BYTES ((ABUF + BBUF + 4*PBUF) * 4)   // 69120 B

__device__ __forceinline__ unsigned packbf(float vhi, float vlo) {
    unsigned r;
    asm("cvt.rn.bf16x2.f32 %0, %1, %2;" : "=r"(r) : "f"(vhi), "f"(vlo));
    return r;
}

// split float pair (v0 = even k, v1 = odd k) -> packed hi, packed residual-lo
__device__ __forceinline__ void split2(float v0, float v1, unsigned &h, unsigned &l) {
    h = packbf(v1, v0);
    float h0 = __uint_as_float(h << 16);
    float h1 = __uint_as_float(h & 0xFFFF0000u);
    l = packbf(v1 - h1, v0 - h0);
}

__device__ __forceinline__ void mma_bf16(float* c, const unsigned* a, const unsigned* b) {
    asm volatile(
        "mma.sync.aligned.m16n8k16.row.col.f32.bf16.bf16.f32 "
        "{%0,%1,%2,%3}, {%4,%5,%6,%7}, {%8,%9}, {%0,%1,%2,%3};"
        : "+f"(c[0]), "+f"(c[1]), "+f"(c[2]), "+f"(c[3])
        : "r"(a[0]), "r"(a[1]), "r"(a[2]), "r"(a[3]), "r"(b[0]), "r"(b[1]));
}

__device__ __forceinline__ void cp16(unsigned saddr, const void* g, unsigned nbytes) {
    asm volatile("cp.async.ca.shared.global [%0], [%1], 16, %2;\n"
                 :: "r"(saddr), "l"(g), "r"(nbytes));
}

template<int ACT>
__global__ __launch_bounds__(256, 2)
void gemm_tc_kernel(const float* __restrict__ A, const float* __restrict__ B,
                    const float* __restrict__ bias, float* __restrict__ C,
                    int M, int N, int K, int ACCUM) {
    extern __shared__ float gsm[];
    float* As = gsm;                         // [GBM][ASTR] fp32 staging
    float* Bs = gsm + ABUF;                  // [GBK][BSTR] fp32 staging
    unsigned* Ah = (unsigned*)(gsm + ABUF + BBUF);           // [16][PSTR]
    unsigned* Al = Ah + PBUF;
    unsigned* Bh = Al + PBUF;
    unsigned* Bl = Bh + PBUF;
    unsigned asBase = (unsigned)__cvta_generic_to_shared(As);
    unsigned bsBase = (unsigned)__cvta_generic_to_shared(Bs);

    int tid  = threadIdx.x;
    int lane = tid & 31;
    int warp = tid >> 5;
    int g  = lane >> 2;
    int tg = lane & 3;
    int wm = (warp & 3) * 32;
    int wn = (warp >> 2) * 64;

    int rowBase = blockIdx.y * GBM;
    int colBase = blockIdx.x * GBN;

    // cp.async mappings
    int am  = tid >> 1;
    int ah4 = (tid & 1) * 16;
    int bk  = tid >> 3;
    int bp  = (tid & 7) * 16;

    const float* gAr = A + (size_t)(rowBase + am) * K + ah4;
    unsigned     aOK = (rowBase + am < M) ? 16u : 0u;
    const float* gBr = B + (size_t)bk * N + colBase + bp;

    // convert mappings (p = tid + 256*j)
    int cm  = tid & 127;        // A row / B col
    int ckp = tid >> 7;         // kpair low bit(s)

    float acc[2][8][4];
    #pragma unroll
    for (int mt = 0; mt < 2; mt++)
        #pragma unroll
        for (int nt = 0; nt < 8; nt++)
            #pragma unroll
            for (int i = 0; i < 4; i++) acc[mt][nt][i] = 0.f;

    int nIter = K / GBK;

    // prologue: cp.async tile 0
    {
        unsigned sa = asBase + (unsigned)((am*ASTR + ah4) * 4);
        unsigned sb = bsBase + (unsigned)((bk*BSTR + bp) * 4);
        #pragma unroll
        for (int j = 0; j < 4; j++) cp16(sa + 16*j, gAr + 4*j, aOK);
        #pragma unroll
        for (int j = 0; j < 4; j++) cp16(sb + 16*j, gBr + 4*j, 16u);
        asm volatile("cp.async.commit_group;\n" ::);
    }

    for (int it = 0; it < nIter; it++) {
        asm volatile("cp.async.wait_group 0;\n" ::);
        __syncthreads();   // staging ready; packed arrays free (prev MMAs done)

        // convert staging -> packed bf16 (each element split exactly once)
        #pragma unroll
        for (int j = 0; j < 8; j++) {
            int kp = ckp + 2*j;            // 0..15
            // A: read As[cm][2kp], As[cm][2kp+1]
            float2 va = *reinterpret_cast<const float2*>(&As[cm*ASTR + 2*kp]);
            unsigned h, l;
            split2(va.x, va.y, h, l);
            Ah[kp*PSTR + cm] = h;
            Al[kp*PSTR + cm] = l;
            // B: read Bs[2kp][cm], Bs[2kp+1][cm]
            float v0 = Bs[(2*kp)   * BSTR + cm];
            float v1 = Bs[(2*kp+1) * BSTR + cm];
            split2(v0, v1, h, l);
            Bh[kp*PSTR + cm] = h;
            Bl[kp*PSTR + cm] = l;
        }
        __syncthreads();   // packed ready; staging free

        // prefetch next tile into staging (overlaps MMAs below)
        if (it + 1 < nIter) {
            int k0n = (it + 1) * GBK;
            unsigned sa = asBase + (unsigned)((am*ASTR + ah4) * 4);
            unsigned sb = bsBase + (unsigned)((bk*BSTR + bp) * 4);
            const float* ga = gAr + k0n;
            const float* gb = gBr + (size_t)k0n * N;
            #pragma unroll
            for (int j = 0; j < 4; j++) cp16(sa + 16*j, ga + 4*j, aOK);
            #pragma unroll
            for (int j = 0; j < 4; j++) cp16(sb + 16*j, gb + 4*j, 16u);
            asm volatile("cp.async.commit_group;\n" ::);
        }

        // MMA loop: pure packed LDS + MMA (no ALU)
        #pragma unroll
        for (int kh = 0; kh < 2; kh++) {           // kpair halves: 0..7, 8..15
            int kp0 = kh * 8;
            unsigned ah[2][4], al[2][4], bh[8][2], bl[8][2];
            #pragma unroll
            for (int mt = 0; mt < 2; mt++) {
                int mb = wm + mt * 16 + g;
                #pragma unroll
                for (int r = 0; r < 4; r++) {
                    int kp = kp0 + tg + (r >> 1) * 4;
                    int row = mb + (r & 1) * 8;
                    ah[mt][r] = Ah[kp*PSTR + row];
                    al[mt][r] = Al[kp*PSTR + row];
                }
            }
            #pragma unroll
            for (int nt = 0; nt < 8; nt++) {
                int n = wn + nt * 8 + g;
                bh[nt][0] = Bh[(kp0 + tg)     * PSTR + n];
                bh[nt][1] = Bh[(kp0 + tg + 4) * PSTR + n];
                bl[nt][0] = Bl[(kp0 + tg)     * PSTR + n];
                bl[nt][1] = Bl[(kp0 + tg + 4) * PSTR + n];
            }
            #pragma unroll
            for (int mt = 0; mt < 2; mt++)
                #pragma unroll
                for (int nt = 0; nt < 8; nt++) {
                    mma_bf16(acc[mt][nt], ah[mt], bh[nt]);   // hi*hi
                    mma_bf16(acc[mt][nt], ah[mt], bl[nt]);   // hi*lo
                    mma_bf16(acc[mt][nt], al[mt], bh[nt]);   // lo*hi
                }
        }
        __syncthreads();   // MMAs done before next convert overwrites packed
    }

    // epilogue
    #pragma unroll
    for (int mt = 0; mt < 2; mt++) {
        int r1 = rowBase + wm + mt * 16 + g;
        int r2 = r1 + 8;
        #pragma unroll
        for (int nt = 0; nt < 8; nt++) {
            int col = colBase + wn + nt * 8 + tg * 2;
            float bv0 = bias ? bias[col]     : 0.f;
            float bv1 = bias ? bias[col + 1] : 0.f;
            #pragma unroll
            for (int half = 0; half < 2; half++) {
                int r = half ? r2 : r1;
                if (r >= M) continue;
                float v0 = acc[mt][nt][half*2 + 0] + bv0;
                float v1 = acc[mt][nt][half*2 + 1] + bv1;
                if (ACT == 1) {
                    v0 = 0.5f * v0 * (1.0f + erff(v0 * 0.70710678118654752f));
                    v1 = 0.5f * v1 * (1.0f + erff(v1 * 0.70710678118654752f));
                }
                if (ACT == 2) { v0 = fmaxf(v0, 0.f); v1 = fmaxf(v1, 0.f); }
                size_t oi = (size_t)r * N + col;
                if (ACCUM) { C[oi] += v0; C[oi + 1] += v1; }
                else       { C[oi]  = v0; C[oi + 1]  = v1; }
            }
        }
    }
}

// ---------------- kernel 7: attention (K transposed in smem, conflict-free) ----------------
#define QT 8
#define SCP 208
#define TOKSP 201
#define ATTN_SMEM_FLOATS (HD*TOKSP + TOKS*HD + QT*HD + QT*SCP + 16)
__global__ void attn_kernel() {
    extern __shared__ float sm[];
    float* Kt = sm;
    float* Vs = Kt + HD*TOKSP;
    float* Qs = Vs + TOKS*HD;
    float* Sc = Qs + QT*HD;
    float* rowinv = Sc + QT*SCP;

    int bh = blockIdx.x;
    int b = bh / NHEAD, h = bh % NHEAD;
    int tid = threadIdx.x;
    const float* base = g_qkv + (size_t)b * TOKS * (3*Dm) + h * HD;

    for (int i = tid; i < TOKS*HD; i += 256) {
        int t = i >> 6, d = i & 63;
        Kt[d*TOKSP + t] = base[(size_t)t*(3*Dm) + Dm   + d];
        Vs[i]           = base[(size_t)t*(3*Dm) + 2*Dm + d];
    }
    __syncthreads();

    for (int q0 = 0; q0 < TOKS; q0 += QT) {
        int qn = min(QT, TOKS - q0);
        for (int i = tid; i < qn*HD; i += 256) {
            int qi = i >> 6, d = i & 63;
            Qs[qi*HD + d] = base[(size_t)(q0 + qi)*(3*Dm) + d];
        }
        __syncthreads();
        for (int qi = 0; qi < qn; qi++) {
            const float* qr = Qs + qi*HD;
            for (int j = tid; j < TOKS; j += 256) {
                float s = 0.f;
                #pragma unroll
                for (int d = 0; d < HD; d++) s += qr[d] * Kt[d*TOKSP + j];
                Sc[qi*SCP + j] = s * 0.125f;
            }
        }
        __syncthreads();
        {
            int w = tid >> 5, lane = tid & 31;
            if (w < qn) {
                float* row = Sc + w*SCP;
                float lm = -1e30f;
                for (int j = lane; j < TOKS; j += 32) lm = fmaxf(lm, row[j]);
                for (int o = 16; o; o >>= 1) lm = fmaxf(lm, __shfl_xor_sync(0xFFFFFFFFu, lm, o));
                float ls = 0.f;
                for (int j = lane; j < TOKS; j += 32) { float e = expf(row[j] - lm); row[j] = e; ls += e; }
                for (int o = 16; o; o >>= 1) ls += __shfl_xor_sync(0xFFFFFFFFu, ls, o);
                if (lane == 0) rowinv[w] = 1.f / ls;
            }
        }
        __syncthreads();
        for (int idx = tid; idx < qn*HD; idx += 256) {
            int qi = idx >> 6, d = idx & 63;
            const float* row = Sc + qi*SCP;
            float acc = 0.f;
            #pragma unroll 4
            for (int j = 0; j < TOKS; j++) acc += row[j] * Vs[j*HD + d];
            g_atto[((size_t)b*TOKS + q0 + qi)*Dm + h*HD + d] = acc * rowinv[qi];
        }
        __syncthreads();
    }
}

// ---------------- host ----------------
extern "C" void kernel_launch(void* const* d_in, const int* in_sizes, int n_in,
                              void* d_out, int out_size) {
    const float* x        = (const float*)d_in[0];
    const float* patch_w  = (const float*)d_in[1];
    const float* patch_b  = (const float*)d_in[2];
    const float* cls_tok  = (const float*)d_in[3];
    const float* pos_emb  = (const float*)d_in[4];
    const float* ln1_s    = (const float*)d_in[5];
    const float* ln1_b    = (const float*)d_in[6];
    const float* qkv_w    = (const float*)d_in[7];
    const float* qkv_b    = (const float*)d_in[8];
    const float* proj_w   = (const float*)d_in[9];
    const float* proj_b   = (const float*)d_in[10];
    const float* ln2_s    = (const float*)d_in[11];
    const float* ln2_b    = (const float*)d_in[12];
    const float* mlp1_w   = (const float*)d_in[13];
    const float* mlp1_b   = (const float*)d_in[14];
    const float* mlp2_w   = (const float*)d_in[15];
    const float* mlp2_b   = (const float*)d_in[16];
    const float* lnf_s    = (const float*)d_in[17];
    const float* lnf_b    = (const float*)d_in[18];
    const float* head_w   = (const float*)d_in[19];
    const float* head_b   = (const float*)d_in[20];
    const float* fc1_w    = (const float*)d_in[21];
    const float* fc1_b    = (const float*)d_in[22];
    const float* fc2_w    = (const float*)d_in[23];
    const float* fc2_b    = (const float*)d_in[24];
    float* out = (float*)d_out;

    float *p_patches, *p_ptok, *p_tok, *p_h, *p_mlp, *p_atto, *p_cls, *p_feat, *p_fc1, *p_qkv;
    cudaGetSymbolAddress((void**)&p_patches, g_patches);
    cudaGetSymbolAddress((void**)&p_ptok,    g_ptok);
    cudaGetSymbolAddress((void**)&p_tok,     g_tok);
    cudaGetSymbolAddress((void**)&p_h,       g_h);
    cudaGetSymbolAddress((void**)&p_mlp,     g_mlp);
    cudaGetSymbolAddress((void**)&p_atto,    g_atto);
    cudaGetSymbolAddress((void**)&p_cls,     g_cls);
    cudaGetSymbolAddress((void**)&p_feat,    g_feat);
    cudaGetSymbolAddress((void**)&p_fc1,     g_fc1);
    cudaGetSymbolAddress((void**)&p_qkv,     g_qkv);

    const int ATTN_SMEM = ATTN_SMEM_FLOATS * (int)sizeof(float);
    cudaFuncSetAttribute(attn_kernel, cudaFuncAttributeMaxDynamicSharedMemorySize, ATTN_SMEM);
    cudaFuncSetAttribute(gemm_tc_kernel<0>, cudaFuncAttributeMaxDynamicSharedMemorySize, GEMM_SMEM_BYTES);
    cudaFuncSetAttribute(gemm_tc_kernel<1>, cudaFuncAttributeMaxDynamicSharedMemorySize, GEMM_SMEM_BYTES);

    float* target_out = (out_size >= Nb*NFRAG*2*2) ? (out + Nb*NFRAG*2) : nullptr;
    rng_kernel<<<1, 512>>>(target_out);

    augment_kernel<<<Nb*NFRAG*3, 256>>>(x);

    {
        int total = Nb*NPT*Dm;
        patchify_kernel<<<(total + 255)/256, 256>>>();
    }

    auto g64  = [](int M, int N) { return dim3((unsigned)((N + 63)/64),  (unsigned)((M + 63)/64)); };
    auto g128 = [](int M, int N) { return dim3((unsigned)(N/128), (unsigned)((M + 127)/128)); };

    gemm_tc_kernel<0><<<g128(Nb*NPT, Dm), 256, GEMM_SMEM_BYTES>>>(p_patches, patch_w, patch_b, p_ptok, Nb*NPT, Dm, Dm, 0);
    {
        int total = Nb*TOKS*Dm;
        assemble_kernel<<<(total + 255)/256, 256>>>(cls_tok, pos_emb);
    }

    for (int l = 0; l < NL; l++) {
        ln_kernel<<<ROWS, 256>>>(p_tok, Dm, ln1_s + (size_t)l*Dm, ln1_b + (size_t)l*Dm, p_h, Dm);
        gemm_tc_kernel<0><<<g128(ROWS, 3*Dm), 256, GEMM_SMEM_BYTES>>>(p_h, qkv_w + (size_t)l*Dm*3*Dm, qkv_b + (size_t)l*3*Dm,
                                                       p_qkv, ROWS, 3*Dm, Dm, 0);
        attn_kernel<<<Nb*NHEAD, 256, ATTN_SMEM>>>();
        gemm_tc_kernel<0><<<g128(ROWS, Dm), 256, GEMM_SMEM_BYTES>>>(p_atto, proj_w + (size_t)l*Dm*Dm, proj_b + (size_t)l*Dm,
                                                     p_tok, ROWS, Dm, Dm, 1);
        ln_kernel<<<ROWS, 256>>>(p_tok, Dm, ln2_s + (size_t)l*Dm, ln2_b + (size_t)l*Dm, p_h, Dm);
        gemm_tc_kernel<1><<<g128(ROWS, MLPD), 256, GEMM_SMEM_BYTES>>>(p_h, mlp1_w + (size_t)l*Dm*MLPD, mlp1_b + (size_t)l*MLPD,
                                                       p_mlp, ROWS, MLPD, Dm, 0);
        gemm_tc_kernel<0><<<g128(ROWS, Dm), 256, GEMM_SMEM_BYTES>>>(p_mlp, mlp2_w + (size_t)l*MLPD*Dm, mlp2_b + (size_t)l*Dm,
                                                     p_tok, ROWS, Dm, MLPD, 1);
    }

    ln_kernel<<<Nb, 256>>>(p_tok, (long long)TOKS*Dm, lnf_s, lnf_b, p_cls, Dm);
    sgemm_kernel<0><<<g64(Nb, NCLS), 256>>>(p_cls, head_w, head_b, p_feat, Nb, NCLS, Dm, 0);
    sgemm_kernel<2><<<g64(Nb, NCLS), 256>>>(p_feat, fc1_w, fc1_b, p_fc1, Nb, NCLS, NCLS, 0);
    sgemm_kernel<0><<<g64(Nb, NFRAG*2), 256>>>(p_fc1, fc2_w, fc2_b, out, Nb, NFRAG*2, NCLS, 0);
}

// round 17
// speedup vs baseline: 1.9476x; 1.9476x over previous
#include <cuda_runtime.h>
#include <math.h>

// ---------------- problem constants ----------------
#define Nb    32
#define Pfr   75
#define NGRID 3
#define NFRAG 9
#define CROPS 64
#define PUZ   225
#define IMGS  224
#define PATCH 16
#define NPT   196
#define Dm    768
#define NHEAD 12
#define HD    64
#define NL    12
#define MLPD  3072
#define NCLS  1000
#define TOKS  197
#define ROWS  (Nb*TOKS)   // 6304

// ---------------- scratch (static device globals; no allocation) ----------------
__device__ float g_img[Nb*3*PUZ*PUZ];
__device__ float g_patches[(size_t)Nb*NPT*Dm];
__device__ float g_ptok[(size_t)Nb*NPT*Dm];
__device__ float g_tok[(size_t)ROWS*Dm];
__device__ float g_h[(size_t)ROWS*Dm];
__device__ float g_qkv[(size_t)ROWS*3*Dm];
__device__ float g_atto[(size_t)ROWS*Dm];
__device__ float g_mlp[(size_t)ROWS*MLPD];
__device__ float g_cls[Nb*Dm];
__device__ float g_feat[Nb*NCLS];
__device__ float g_fc1[Nb*NCLS];
__device__ int   g_shuffle[Nb*NFRAG];
__device__ int   g_offs[Nb*NFRAG*2];
__device__ int   g_jitt[Nb*NFRAG*3];

// ---------------- threefry2x32 (KAT-verified core) ----------------
__device__ __forceinline__ void threefry(unsigned k0, unsigned k1, unsigned &x0, unsigned &x1) {
    unsigned ks0 = k0, ks1 = k1, ks2 = k0 ^ k1 ^ 0x1BD11BDAu;
    x0 += ks0; x1 += ks1;
#define TFRND(r) { x0 += x1; x1 = (x1 << (r)) | (x1 >> (32 - (r))); x1 ^= x0; }
    TFRND(13) TFRND(15) TFRND(26) TFRND(6);  x0 += ks1; x1 += ks2 + 1u;
    TFRND(17) TFRND(29) TFRND(16) TFRND(24); x0 += ks2; x1 += ks0 + 2u;
    TFRND(13) TFRND(15) TFRND(26) TFRND(6);  x0 += ks0; x1 += ks1 + 3u;
    TFRND(17) TFRND(29) TFRND(16) TFRND(24); x0 += ks1; x1 += ks2 + 4u;
    TFRND(13) TFRND(15) TFRND(26) TFRND(6);  x0 += ks2; x1 += ks0 + 5u;
#undef TFRND
}

__device__ __forceinline__ unsigned rb32_part(unsigned k0, unsigned k1, unsigned i) {
    unsigned x0 = 0u, x1 = i;
    threefry(k0, k1, x0, x1);
    return x0 ^ x1;
}

__device__ __forceinline__ void split_key(unsigned k0, unsigned k1, unsigned t,
                                          unsigned &o0, unsigned &o1) {
    unsigned x0 = 0u, x1 = t;
    threefry(k0, k1, x0, x1);
    o0 = x0; o1 = x1;
}

// ---------------- kernel 1: RNG setup + target output ----------------
__global__ void rng_kernel(float* target_out) {
    __shared__ unsigned keys[14];
    __shared__ float noise[Nb*NFRAG];
    int tid = threadIdx.x;

    if (tid == 0) {
        for (int t = 0; t < 3; t++)
            split_key(0u, 42u, (unsigned)t, keys[2*t], keys[2*t+1]);
        split_key(keys[2], keys[3], 0u, keys[6],  keys[7]);
        split_key(keys[2], keys[3], 1u, keys[8],  keys[9]);
        split_key(keys[4], keys[5], 0u, keys[10], keys[11]);
        split_key(keys[4], keys[5], 1u, keys[12], keys[13]);
    }
    __syncthreads();

    if (tid < Nb*NFRAG) {
        unsigned bits = rb32_part(keys[0], keys[1], (unsigned)tid);
        noise[tid] = __uint_as_float((bits >> 9) | 0x3F800000u) - 1.0f;
    }
    __syncthreads();

    if (tid < Nb) {
        int ids[NFRAG];
        unsigned used = 0;
        for (int r = 0; r < NFRAG; r++) {
            int best = -1;
            for (int j = 0; j < NFRAG; j++) {
                if (used & (1u << j)) continue;
                if (best < 0 || noise[tid*NFRAG + j] < noise[tid*NFRAG + best]) best = j;
            }
            ids[r] = best; used |= (1u << best);
        }
        int rest[NFRAG];
        for (int r = 0; r < NFRAG; r++) { g_shuffle[tid*NFRAG + r] = ids[r]; rest[ids[r]] = r; }
        if (target_out) {
            for (int f = 0; f < NFRAG; f++) {
                target_out[(tid*NFRAG + f)*2 + 0] = (float)(rest[f] / 3);
                target_out[(tid*NFRAG + f)*2 + 1] = (float)(rest[f] % 3);
            }
        }
    }

    for (int i = tid; i < Nb*NFRAG*2; i += blockDim.x) {
        unsigned hi = rb32_part(keys[6], keys[7], (unsigned)i);
        unsigned lo = rb32_part(keys[8], keys[9], (unsigned)i);
        unsigned v = (((hi % 12u) * 4u) + (lo % 12u)) % 12u;
        g_offs[i] = (int)v;
    }
    for (int i = tid; i < Nb*NFRAG*3; i += blockDim.x) {
        unsigned hi = rb32_part(keys[10], keys[11], (unsigned)i);
        unsigned lo = rb32_part(keys[12], keys[13], (unsigned)i);
        unsigned v = ((hi % 5u) + (lo % 5u)) % 5u;
        g_jitt[i] = (int)v - 2;
    }
}

// ---------------- block reductions (blockDim == 256) ----------------
__device__ __forceinline__ float bsum256(float v, float* red8) {
    for (int o = 16; o; o >>= 1) v += __shfl_xor_sync(0xFFFFFFFFu, v, o);
    if ((threadIdx.x & 31) == 0) red8[threadIdx.x >> 5] = v;
    __syncthreads();
    float r = red8[0]+red8[1]+red8[2]+red8[3]+red8[4]+red8[5]+red8[6]+red8[7];
    __syncthreads();
    return r;
}

// ---------------- kernel 2: augment ----------------
__global__ void augment_kernel(const float* __restrict__ x) {
    __shared__ float buf[Pfr*Pfr];
    __shared__ float red8[8];
    int bfc = blockIdx.x;
    int c = bfc % 3;
    int bf = bfc / 3;
    int b = bf / NFRAG, f = bf % NFRAG;

    int src = g_shuffle[bf];
    int sr = (src / 3) * Pfr + g_offs[2*bf + 0];
    int sc = (src % 3) * Pfr + g_offs[2*bf + 1];
    float jitv = (float)g_jitt[bf*3 + c];
    const float* xp = x + ((size_t)b*3 + c) * PUZ * PUZ;

    const float sf = 64.0f / 75.0f;
    float lsum = 0.f;
    for (int idx = threadIdx.x; idx < Pfr*Pfr; idx += 256) {
        int i = idx / Pfr, j = idx % Pfr;
        float fy = (i + 0.5f) * sf - 0.5f;
        float fx = (j + 0.5f) * sf - 0.5f;
        int   y0 = (int)floorf(fy); float dy = fy - (float)y0;
        int   x0 = (int)floorf(fx); float dx = fx - (float)x0;
        int y0c = max(0, min(63, y0)),   y1c = max(0, min(63, y0 + 1));
        int x0c = max(0, min(63, x0)),   x1c = max(0, min(63, x0 + 1));
        const float* r0 = xp + (size_t)(sr + y0c) * PUZ + sc;
        const float* r1 = xp + (size_t)(sr + y1c) * PUZ + sc;
        float v = (1.f-dy)*((1.f-dx)*r0[x0c] + dx*r0[x1c])
                +       dy*((1.f-dx)*r1[x0c] + dx*r1[x1c]);
        v = v + jitv;
        v = fminf(fmaxf(v, 0.f), 255.f);
        buf[idx] = v;
        lsum += v;
    }
    float m = bsum256(lsum, red8) * (1.0f / (Pfr*Pfr));
    float lss = 0.f;
    for (int idx = threadIdx.x; idx < Pfr*Pfr; idx += 256) {
        float d = buf[idx] - m;
        lss += d * d;
    }
    float ss = bsum256(lss, red8);
    float s = sqrtf(ss / (float)(Pfr*Pfr - 1));
    if (s == 0.f) s = 1.f;

    int gi = f / 3, gj = f % 3;
    float* op = g_img + ((size_t)b*3 + c) * PUZ * PUZ + (size_t)gi*Pfr*PUZ + gj*Pfr;
    for (int idx = threadIdx.x; idx < Pfr*Pfr; idx += 256) {
        op[(idx / Pfr) * PUZ + (idx % Pfr)] = (buf[idx] - m) / s;
    }
}

// ---------------- kernel 3: patchify ----------------
__global__ void patchify_kernel() {
    int idx = blockIdx.x * blockDim.x + threadIdx.x;
    if (idx >= Nb*NPT*Dm) return;
    int k = idx % Dm;
    int p = (idx / Dm) % NPT;
    int b = idx / (Dm * NPT);
    int c = k >> 8, u = (k >> 4) & 15, v = k & 15;
    int pi = p / 14, pj = p % 14;
    g_patches[idx] = g_img[(((size_t)b*3 + c) * PUZ + (pi*16 + u)) * PUZ + (pj*16 + v)];
}

// ---------------- kernel 4: token assemble ----------------
__global__ void assemble_kernel(const float* __restrict__ clstok, const float* __restrict__ pos) {
    int idx = blockIdx.x * blockDim.x + threadIdx.x;
    if (idx >= Nb*TOKS*Dm) return;
    int d = idx % Dm;
    int t = (idx / Dm) % TOKS;
    int b = idx / (Dm * TOKS);
    float v = (t == 0) ? clstok[d] : g_ptok[((size_t)b*NPT + (t-1))*Dm + d];
    g_tok[idx] = v + pos[t*Dm + d];
}

// ---------------- kernel 5: layernorm ----------------
__global__ void ln_kernel(const float* __restrict__ x, long long sx,
                          const float* __restrict__ s, const float* __restrict__ b,
                          float* __restrict__ y, long long sy) {
    __shared__ float red8[8];
    const float* xr = x + (long long)blockIdx.x * sx;
    float* yr = y + (long long)blockIdx.x * sy;
    int t = threadIdx.x;
    float v0 = xr[t], v1 = xr[t+256], v2 = xr[t+512];
    float m = bsum256(v0+v1+v2, red8) * (1.0f/768.0f);
    float d0 = v0-m, d1 = v1-m, d2 = v2-m;
    float var = bsum256(d0*d0 + d1*d1 + d2*d2, red8) * (1.0f/768.0f);
    float inv = rsqrtf(var + 1e-6f);
    yr[t]     = d0*inv*s[t]     + b[t];
    yr[t+256] = d1*inv*s[t+256] + b[t+256];
    yr[t+512] = d2*inv*s[t+512] + b[t+512];
}

// ---------------- kernel 6a: small fp32 SGEMM (head only) ----------------
template<int ACT>
__global__ void sgemm_kernel(const float* __restrict__ A, const float* __restrict__ B,
                             const float* __restrict__ bias, float* __restrict__ C,
                             int M, int N, int K, int ACCUM) {
    __shared__ float As[16][64];
    __shared__ float Bs[16][64];
    int tid = threadIdx.x;
    int tx = tid & 15, ty = tid >> 4;
    int blockRow = blockIdx.y * 64;
    int blockCol = blockIdx.x * 64;
    float acc[4][4] = {};

    for (int k0 = 0; k0 < K; k0 += 16) {
        #pragma unroll
        for (int t = tid; t < 64*16; t += 256) {
            int m  = t >> 4, kk  = t & 15;
            int gr = blockRow + m, gc = k0 + kk;
            As[kk][m] = (gr < M && gc < K) ? A[(size_t)gr*K + gc] : 0.f;
            int kk2 = t >> 6, nn = t & 63;
            int gr2 = k0 + kk2, gc2 = blockCol + nn;
            Bs[kk2][nn] = (gr2 < K && gc2 < N) ? B[(size_t)gr2*N + gc2] : 0.f;
        }
        __syncthreads();
        #pragma unroll
        for (int kk = 0; kk < 16; kk++) {
            float a[4], bb[4];
            #pragma unroll
            for (int i = 0; i < 4; i++) a[i]  = As[kk][ty*4 + i];
            #pragma unroll
            for (int j = 0; j < 4; j++) bb[j] = Bs[kk][tx*4 + j];
            #pragma unroll
            for (int i = 0; i < 4; i++)
                #pragma unroll
                for (int j = 0; j < 4; j++)
                    acc[i][j] += a[i] * bb[j];
        }
        __syncthreads();
    }

    #pragma unroll
    for (int i = 0; i < 4; i++) {
        int r = blockRow + ty*4 + i;
        if (r >= M) continue;
        #pragma unroll
        for (int j = 0; j < 4; j++) {
            int cc = blockCol + tx*4 + j;
            if (cc >= N) continue;
            float v = acc[i][j] + (bias ? bias[cc] : 0.f);
            if (ACT == 1) v = 0.5f * v * (1.0f + erff(v * 0.70710678118654752f));
            if (ACT == 2) v = fmaxf(v, 0.f);
            size_t oi = (size_t)r * N + cc;
            if (ACCUM) C[oi] += v; else C[oi] = v;
        }
    }
}

// ---------------- kernel 6b: bf16x3 GEMM (m16n8k16), cp.async double-buffered ----------------
// (R15 version — best measured GEMM)
#define GBM 128
#define GBN 128
#define GBK 32
#define ASTR 36
#define BSTR 132
#define ABUF (GBM*ASTR)
#define BBUF (GBK*BSTR)
#define GEMM_SMEM_BYTES ((2*ABUF + 2*BBUF) * 4)   // 70656 B

__device__ __forceinline__ unsigned packbf(float vhi, float vlo) {
    unsigned r;
    asm("cvt.rn.bf16x2.f32 %0, %1, %2;" : "=r"(r) : "f"(vhi), "f"(vlo));
    return r;
}

__device__ __forceinline__ void split2(float v0, float v1, unsigned &h, unsigned &l) {
    h = packbf(v1, v0);
    float h0 = __uint_as_float(h << 16);
    float h1 = __uint_as_float(h & 0xFFFF0000u);
    l = packbf(v1 - h1, v0 - h0);
}

__device__ __forceinline__ void mma_bf16(float* c, const unsigned* a, const unsigned* b) {
    asm volatile(
        "mma.sync.aligned.m16n8k16.row.col.f32.bf16.bf16.f32 "
        "{%0,%1,%2,%3}, {%4,%5,%6,%7}, {%8,%9}, {%0,%1,%2,%3};"
        : "+f"(c[0]), "+f"(c[1]), "+f"(c[2]), "+f"(c[3])
        : "r"(a[0]), "r"(a[1]), "r"(a[2]), "r"(a[3]), "r"(b[0]), "r"(b[1]));
}

__device__ __forceinline__ void cp16(unsigned saddr, const void* g, unsigned nbytes) {
    asm volatile("cp.async.ca.shared.global [%0], [%1], 16, %2;\n"
                 :: "r"(saddr), "l"(g), "r"(nbytes));
}

template<int ACT>
__global__ __launch_bounds__(256, 2)
void gemm_tc_kernel(const float* __restrict__ A, const float* __restrict__ B,
                    const float* __restrict__ bias, float* __restrict__ C,
                    int M, int N, int K, int ACCUM) {
    extern __shared__ float gsm[];
    float* As = gsm;
    float* Bs = gsm + 2*ABUF;
    unsigned asBase = (unsigned)__cvta_generic_to_shared(As);
    unsigned bsBase = (unsigned)__cvta_generic_to_shared(Bs);

    int tid  = threadIdx.x;
    int lane = tid & 31;
    int warp = tid >> 5;
    int g  = lane >> 2;
    int tg = lane & 3;
    int wm = (warp & 3) * 32;
    int wn = (warp >> 2) * 64;

    int rowBase = blockIdx.y * GBM;
    int colBase = blockIdx.x * GBN;

    int am  = tid >> 1;
    int ah4 = (tid & 1) * 16;
    int bk  = tid >> 3;
    int bp  = (tid & 7) * 16;

    const float* gAr = A + (size_t)(rowBase + am) * K + ah4;
    unsigned     aOK = (rowBase + am < M) ? 16u : 0u;
    const float* gBr = B + (size_t)bk * N + colBase + bp;

    float acc[2][8][4];
    #pragma unroll
    for (int mt = 0; mt < 2; mt++)
        #pragma unroll
        for (int nt = 0; nt < 8; nt++)
            #pragma unroll
            for (int i = 0; i < 4; i++) acc[mt][nt][i] = 0.f;

    int nIter = K / GBK;

    {
        unsigned sa = asBase + (unsigned)((am*ASTR + ah4) * 4);
        unsigned sb = bsBase + (unsigned)((bk*BSTR + bp) * 4);
        #pragma unroll
        for (int j = 0; j < 4; j++) cp16(sa + 16*j, gAr + 4*j, aOK);
        #pragma unroll
        for (int j = 0; j < 4; j++) cp16(sb + 16*j, gBr + 4*j, 16u);
        asm volatile("cp.async.commit_group;\n" ::);
    }

    for (int it = 0; it < nIter; it++) {
        int buf = it & 1;
        if (it + 1 < nIter) {
            int nb = (it + 1) & 1;
            int k0n = (it + 1) * GBK;
            unsigned sa = asBase + (unsigned)((nb*ABUF + am*ASTR + ah4) * 4);
            unsigned sb = bsBase + (unsigned)((nb*BBUF + bk*BSTR + bp) * 4);
            const float* ga = gAr + k0n;
            const float* gb = gBr + (size_t)k0n * N;
            #pragma unroll
            for (int j = 0; j < 4; j++) cp16(sa + 16*j, ga + 4*j, aOK);
            #pragma unroll
            for (int j = 0; j < 4; j++) cp16(sb + 16*j, gb + 4*j, 16u);
            asm volatile("cp.async.commit_group;\n" ::);
            asm volatile("cp.async.wait_group 1;\n" ::);
        } else {
            asm volatile("cp.async.wait_group 0;\n" ::);
        }
        __syncthreads();

        const float* Ab = As + buf*ABUF;
        const float* Bb = Bs + buf*BBUF;

        #pragma unroll
        for (int kk = 0; kk < GBK; kk += 16) {
            unsigned ah[2][4], al[2][4], bh[8][2], bl[8][2];
            #pragma unroll
            for (int mt = 0; mt < 2; mt++) {
                int mb = wm + mt * 16;
                #pragma unroll
                for (int r = 0; r < 4; r++) {
                    int row = mb + g + (r & 1) * 8;
                    int kc  = kk + 2*tg + (r >> 1) * 8;
                    float2 v = *reinterpret_cast<const float2*>(&Ab[row*ASTR + kc]);
                    split2(v.x, v.y, ah[mt][r], al[mt][r]);
                }
            }
            #pragma unroll
            for (int nt = 0; nt < 8; nt++) {
                int n = wn + nt * 8 + g;
                float v0 = Bb[(kk + 2*tg)     * BSTR + n];
                float v1 = Bb[(kk + 2*tg + 1) * BSTR + n];
                float w0 = Bb[(kk + 2*tg + 8) * BSTR + n];
                float w1 = Bb[(kk + 2*tg + 9) * BSTR + n];
                split2(v0, v1, bh[nt][0], bl[nt][0]);
                split2(w0, w1, bh[nt][1], bl[nt][1]);
            }
            #pragma unroll
            for (int mt = 0; mt < 2; mt++)
                #pragma unroll
                for (int nt = 0; nt < 8; nt++) {
                    mma_bf16(acc[mt][nt], ah[mt], bh[nt]);
                    mma_bf16(acc[mt][nt], ah[mt], bl[nt]);
                    mma_bf16(acc[mt][nt], al[mt], bh[nt]);
                }
        }
        __syncthreads();
    }

    #pragma unroll
    for (int mt = 0; mt < 2; mt++) {
        int r1 = rowBase + wm + mt * 16 + g;
        int r2 = r1 + 8;
        #pragma unroll
        for (int nt = 0; nt < 8; nt++) {
            int col = colBase + wn + nt * 8 + tg * 2;
            float bv0 = bias ? bias[col]     : 0.f;
            float bv1 = bias ? bias[col + 1] : 0.f;
            #pragma unroll
            for (int half = 0; half < 2; half++) {
                int r = half ? r2 : r1;
                if (r >= M) continue;
                float v0 = acc[mt][nt][half*2 + 0] + bv0;
                float v1 = acc[mt][nt][half*2 + 1] + bv1;
                if (ACT == 1) {
                    v0 = 0.5f * v0 * (1.0f + erff(v0 * 0.70710678118654752f));
                    v1 = 0.5f * v1 * (1.0f + erff(v1 * 0.70710678118654752f));
                }
                if (ACT == 2) { v0 = fmaxf(v0, 0.f); v1 = fmaxf(v1, 0.f); }
                size_t oi = (size_t)r * N + col;
                if (ACCUM) { C[oi] += v0; C[oi + 1] += v1; }
                else       { C[oi]  = v0; C[oi + 1]  = v1; }
            }
        }
    }
}

// ---------------- kernel 7: attention (vectorized float4 phases) ----------------
#define QT 8
#define SCP 208
#define TOKSP 204   // %4==0 for float4 loads; conflict-free row access
#define NCH  ((TOKS + 3) / 4)   // 50 chunks of 4 j's
#define ATTN_SMEM_FLOATS (HD*TOKSP + TOKS*HD + QT*HD + QT*SCP + 16)
__global__ void attn_kernel() {
    extern __shared__ float sm[];
    float* Kt = sm;                 // [HD][TOKSP]
    float* Vs = Kt + HD*TOKSP;      // [TOKS][HD]
    float* Qs = Vs + TOKS*HD;       // [QT][HD]
    float* Sc = Qs + QT*HD;         // [QT][SCP]
    float* rowinv = Sc + QT*SCP;

    int bh = blockIdx.x;
    int b = bh / NHEAD, h = bh % NHEAD;
    int tid = threadIdx.x;
    const float* base = g_qkv + (size_t)b * TOKS * (3*Dm) + h * HD;

    for (int i = tid; i < TOKS*HD; i += 256) {
        int t = i >> 6, d = i & 63;
        Kt[d*TOKSP + t] = base[(size_t)t*(3*Dm) + Dm   + d];
        Vs[i]           = base[(size_t)t*(3*Dm) + 2*Dm + d];
    }
    // zero Kt tail columns (j = TOKS..TOKSP-1) so float4 tail reads are safe
    for (int i = tid; i < HD*(TOKSP - TOKS); i += 256) {
        int d = i / (TOKSP - TOKS), j = TOKS + i % (TOKSP - TOKS);
        Kt[d*TOKSP + j] = 0.f;
    }
    __syncthreads();

    for (int q0 = 0; q0 < TOKS; q0 += QT) {
        int qn = min(QT, TOKS - q0);
        for (int i = tid; i < qn*HD; i += 256) {
            int qi = i >> 6, d = i & 63;
            Qs[qi*HD + d] = base[(size_t)(q0 + qi)*(3*Dm) + d];
        }
        __syncthreads();
        // scores: each thread computes 4 consecutive j via float4 (Kt row)
        for (int idx = tid; idx < qn*NCH; idx += 256) {
            int qi = idx / NCH;
            int j  = (idx % NCH) * 4;
            const float* qr = Qs + qi*HD;
            float s0 = 0.f, s1 = 0.f, s2 = 0.f, s3 = 0.f;
            #pragma unroll
            for (int d = 0; d < HD; d++) {
                float qd = qr[d];
                float4 kv = *reinterpret_cast<const float4*>(&Kt[d*TOKSP + j]);
                s0 += qd * kv.x; s1 += qd * kv.y; s2 += qd * kv.z; s3 += qd * kv.w;
            }
            float4 sv = make_float4(s0*0.125f, s1*0.125f, s2*0.125f, s3*0.125f);
            *reinterpret_cast<float4*>(&Sc[qi*SCP + j]) = sv;
        }
        __syncthreads();
        {
            int w = tid >> 5, lane = tid & 31;
            if (w < qn) {
                float* row = Sc + w*SCP;
                float lm = -1e30f;
                for (int j = lane; j < TOKS; j += 32) lm = fmaxf(lm, row[j]);
                for (int o = 16; o; o >>= 1) lm = fmaxf(lm, __shfl_xor_sync(0xFFFFFFFFu, lm, o));
                float ls = 0.f;
                for (int j = lane; j < TOKS; j += 32) { float e = expf(row[j] - lm); row[j] = e; ls += e; }
                for (int o = 16; o; o >>= 1) ls += __shfl_xor_sync(0xFFFFFFFFu, ls, o);
                if (lane == 0) rowinv[w] = 1.f / ls;
            }
        }
        __syncthreads();
        // AV: each thread computes 4 consecutive d via float4 (Vs row)
        for (int idx = tid; idx < qn*(HD/4); idx += 256) {
            int qi = idx / (HD/4);
            int d  = (idx % (HD/4)) * 4;
            const float* row = Sc + qi*SCP;
            float a0 = 0.f, a1 = 0.f, a2 = 0.f, a3 = 0.f;
            for (int j = 0; j < TOKS; j++) {
                float rj = row[j];
                float4 vv = *reinterpret_cast<const float4*>(&Vs[j*HD + d]);
                a0 += rj * vv.x; a1 += rj * vv.y; a2 += rj * vv.z; a3 += rj * vv.w;
            }
            float inv = rowinv[qi];
            float4 ov = make_float4(a0*inv, a1*inv, a2*inv, a3*inv);
            *reinterpret_cast<float4*>(&g_atto[((size_t)b*TOKS + q0 + qi)*Dm + h*HD + d]) = ov;
        }
        __syncthreads();
    }
}

// ---------------- host ----------------
extern "C" void kernel_launch(void* const* d_in, const int* in_sizes, int n_in,
                              void* d_out, int out_size) {
    const float* x        = (const float*)d_in[0];
    const float* patch_w  = (const float*)d_in[1];
    const float* patch_b  = (const float*)d_in[2];
    const float* cls_tok  = (const float*)d_in[3];
    const float* pos_emb  = (const float*)d_in[4];
    const float* ln1_s    = (const float*)d_in[5];
    const float* ln1_b    = (const float*)d_in[6];
    const float* qkv_w    = (const float*)d_in[7];
    const float* qkv_b    = (const float*)d_in[8];
    const float* proj_w   = (const float*)d_in[9];
    const float* proj_b   = (const float*)d_in[10];
    const float* ln2_s    = (const float*)d_in[11];
    const float* ln2_b    = (const float*)d_in[12];
    const float* mlp1_w   = (const float*)d_in[13];
    const float* mlp1_b   = (const float*)d_in[14];
    const float* mlp2_w   = (const float*)d_in[15];
    const float* mlp2_b   = (const float*)d_in[16];
    const float* lnf_s    = (const float*)d_in[17];
    const float* lnf_b    = (const float*)d_in[18];
    const float* head_w   = (const float*)d_in[19];
    const float* head_b   = (const float*)d_in[20];
    const float* fc1_w    = (const float*)d_in[21];
    const float* fc1_b    = (const float*)d_in[22];
    const float* fc2_w    = (const float*)d_in[23];
    const float* fc2_b    = (const float*)d_in[24];
    float* out = (float*)d_out;

    float *p_patches, *p_ptok, *p_tok, *p_h, *p_mlp, *p_atto, *p_cls, *p_feat, *p_fc1, *p_qkv;
    cudaGetSymbolAddress((void**)&p_patches, g_patches);
    cudaGetSymbolAddress((void**)&p_ptok,    g_ptok);
    cudaGetSymbolAddress((void**)&p_tok,     g_tok);
    cudaGetSymbolAddress((void**)&p_h,       g_h);
    cudaGetSymbolAddress((void**)&p_mlp,     g_mlp);
    cudaGetSymbolAddress((void**)&p_atto,    g_atto);
    cudaGetSymbolAddress((void**)&p_cls,     g_cls);
    cudaGetSymbolAddress((void**)&p_feat,    g_feat);
    cudaGetSymbolAddress((void**)&p_fc1,     g_fc1);
    cudaGetSymbolAddress((void**)&p_qkv,     g_qkv);

    const int ATTN_SMEM = ATTN_SMEM_FLOATS * (int)sizeof(float);
    cudaFuncSetAttribute(attn_kernel, cudaFuncAttributeMaxDynamicSharedMemorySize, ATTN_SMEM);
    cudaFuncSetAttribute(gemm_tc_kernel<0>, cudaFuncAttributeMaxDynamicSharedMemorySize, GEMM_SMEM_BYTES);
    cudaFuncSetAttribute(gemm_tc_kernel<1>, cudaFuncAttributeMaxDynamicSharedMemorySize, GEMM_SMEM_BYTES);

    float* target_out = (out_size >= Nb*NFRAG*2*2) ? (out + Nb*NFRAG*2) : nullptr;
    rng_kernel<<<1, 512>>>(target_out);

    augment_kernel<<<Nb*NFRAG*3, 256>>>(x);

    {
        int total = Nb*NPT*Dm;
        patchify_kernel<<<(total + 255)/256, 256>>>();
    }

    auto g64  = [](int M, int N) { return dim3((unsigned)((N + 63)/64),  (unsigned)((M + 63)/64)); };
    auto g128 = [](int M, int N) { return dim3((unsigned)(N/128), (unsigned)((M + 127)/128)); };

    gemm_tc_kernel<0><<<g128(Nb*NPT, Dm), 256, GEMM_SMEM_BYTES>>>(p_patches, patch_w, patch_b, p_ptok, Nb*NPT, Dm, Dm, 0);
    {
        int total = Nb*TOKS*Dm;
        assemble_kernel<<<(total + 255)/256, 256>>>(cls_tok, pos_emb);
    }

    for (int l = 0; l < NL; l++) {
        ln_kernel<<<ROWS, 256>>>(p_tok, Dm, ln1_s + (size_t)l*Dm, ln1_b + (size_t)l*Dm, p_h, Dm);
        gemm_tc_kernel<0><<<g128(ROWS, 3*Dm), 256, GEMM_SMEM_BYTES>>>(p_h, qkv_w + (size_t)l*Dm*3*Dm, qkv_b + (size_t)l*3*Dm,
                                                       p_qkv, ROWS, 3*Dm, Dm, 0);
        attn_kernel<<<Nb*NHEAD, 256, ATTN_SMEM>>>();
        gemm_tc_kernel<0><<<g128(ROWS, Dm), 256, GEMM_SMEM_BYTES>>>(p_atto, proj_w + (size_t)l*Dm*Dm, proj_b + (size_t)l*Dm,
                                                     p_tok, ROWS, Dm, Dm, 1);
        ln_kernel<<<ROWS, 256>>>(p_tok, Dm, ln2_s + (size_t)l*Dm, ln2_b + (size_t)l*Dm, p_h, Dm);
        gemm_tc_kernel<1><<<g128(ROWS, MLPD), 256, GEMM_SMEM_BYTES>>>(p_h, mlp1_w + (size_t)l*Dm*MLPD, mlp1_b + (size_t)l*MLPD,
                                                       p_mlp, ROWS, MLPD, Dm, 0);
        gemm_tc_kernel<0><<<g128(ROWS, Dm), 256, GEMM_SMEM_BYTES>>>(p_mlp, mlp2_w + (size_t)l*MLPD*Dm, mlp2_b + (size_t)l*Dm,
                                                     p_tok, ROWS, Dm, MLPD, 1);
    }

    ln_kernel<<<Nb, 256>>>(p_tok, (long long)TOKS*Dm, lnf_s, lnf_b, p_cls, Dm);
    sgemm_kernel<0><<<g64(Nb, NCLS), 256>>>(p_cls, head_w, head_b, p_feat, Nb, NCLS, Dm, 0);
    sgemm_kernel<2><<<g64(Nb, NCLS), 256>>>(p_feat, fc1_w, fc1_b, p_fc1, Nb, NCLS, NCLS, 0);
    sgemm_kernel<0><<<g64(Nb, NFRAG*2), 256>>>(p_fc1, fc2_w, fc2_b, out, Nb, NFRAG*2, NCLS, 0);
}